// round 7
// baseline (speedup 1.0000x reference)
#include <cuda_runtime.h>

#define NN 100000
#define NE 1600000
#define IND 128
#define HD 64
#define SCAN_BLOCKS 391   // ceil(NN/256)

// -------- scratch (no allocation allowed: __device__ globals) --------
__device__ int   g_deg_out[NN];
__device__ int   g_deg_in[NN];
__device__ int   g_start[NN];     // CSR row start (exclusive scan of deg_in)
__device__ int   g_cursor[NN];    // placement cursors
__device__ int   g_bsum[SCAN_BLOCKS];
__device__ __align__(16) int g_esrc[NE];   // edge sources grouped by dst
__device__ float g_norm_src[NN];
__device__ float g_norm_dst[NN];
__device__ __align__(16) float g_x1[NN * HD];   // projected layer-1 features
__device__ __align__(16) float g_agg1[NN * HD]; // layer-1 aggregation
__device__ __align__(16) float g_x2[NN * HD];   // projected layer-2 features

// -------- init: zero integer degree counters --------
__global__ void k_init() {
    int i = blockIdx.x * blockDim.x + threadIdx.x;
    if (i < NN) {
        g_deg_out[i] = 0;
        g_deg_in[i] = 0;
    }
}

// -------- integer degree histograms --------
__global__ void k_deg(const int* __restrict__ src, const int* __restrict__ dst) {
    int i = blockIdx.x * blockDim.x + threadIdx.x;
    if (i < NE) {
        atomicAdd(&g_deg_out[src[i]], 1);
        atomicAdd(&g_deg_in[dst[i]], 1);
    }
}

// -------- exclusive scan of deg_in -> g_start (3 kernels) --------
__global__ void k_scan1() {
    __shared__ int s[256];
    int tid = threadIdx.x;
    int i = blockIdx.x * 256 + tid;
    int v = (i < NN) ? g_deg_in[i] : 0;
    s[tid] = v;
    __syncthreads();
    for (int off = 1; off < 256; off <<= 1) {
        int t = (tid >= off) ? s[tid - off] : 0;
        __syncthreads();
        s[tid] += t;
        __syncthreads();
    }
    if (i < NN) g_start[i] = s[tid] - v;          // block-local exclusive
    if (tid == 255) g_bsum[blockIdx.x] = s[255];  // block total
}

__global__ void k_scan2() {  // single block of 512: exclusive scan of block sums
    __shared__ int s[512];
    int tid = threadIdx.x;
    int v = (tid < SCAN_BLOCKS) ? g_bsum[tid] : 0;
    s[tid] = v;
    __syncthreads();
    for (int off = 1; off < 512; off <<= 1) {
        int t = (tid >= off) ? s[tid - off] : 0;
        __syncthreads();
        s[tid] += t;
        __syncthreads();
    }
    if (tid < SCAN_BLOCKS) g_bsum[tid] = s[tid] - v;  // exclusive
}

// scan finalize + norms (fused)
__global__ void k_scan3() {
    int i = blockIdx.x * blockDim.x + threadIdx.x;
    if (i < NN) {
        int st = g_start[i] + g_bsum[i >> 8];
        g_start[i] = st;
        g_cursor[i] = st;
        g_norm_src[i] = rsqrtf(fmaxf((float)g_deg_out[i], 1.f));
        g_norm_dst[i] = rsqrtf(fmaxf((float)g_deg_in[i], 1.f));
    }
}

// -------- CSR placement: group edge sources by dst --------
__global__ void k_place(const int* __restrict__ src, const int* __restrict__ dst) {
    int i = blockIdx.x * blockDim.x + threadIdx.x;
    if (i < NE) {
        int d = dst[i];
        int pos = atomicAdd(&g_cursor[d], 1);
        g_esrc[pos] = src[i];
    }
}

// ============================================================================
// GEMM1: g_x1 = (h * norm_src) @ W1   [100000x128 @ 128x64]
// 128-row x 64-col tile, 256 threads, 8x4 register tile per thread.
// K staged in chunks of 32. Transposed act tile, stride 132 (16B aligned,
// enables LDS.128 broadcast loads; 3 LDS per 32 FFMA).
// ============================================================================
#define KC2 32
#define HSTR2 132

__global__ __launch_bounds__(256) void k_gemm1(const float* __restrict__ h,
                                               const float* __restrict__ W1) {
    __shared__ __align__(16) float Wc[KC2 * HD];       // 8 KB   [kk][c]
    __shared__ __align__(16) float hsT[KC2 * HSTR2];   // 16.5 KB [kk][r]
    int tid = threadIdx.x;
    int ty = tid >> 4;      // 0..15 -> rows 8*ty..8*ty+7
    int tx = tid & 15;      // 0..15 -> cols 4*tx..4*tx+3
    int row0 = blockIdx.x * 128;

    float acc[8][4];
#pragma unroll
    for (int j = 0; j < 8; j++)
#pragma unroll
        for (int c = 0; c < 4; c++) acc[j][c] = 0.f;

#pragma unroll 1
    for (int kc = 0; kc < IND / KC2; kc++) {
        int k0 = kc * KC2;
        __syncthreads();
        // stage W chunk (2048 floats, coalesced)
        for (int i = tid; i < KC2 * HD; i += 256)
            Wc[i] = W1[k0 * HD + i];
        // stage h chunk transposed: warp reads 32 consecutive k of one row
        for (int i = tid; i < 128 * KC2; i += 256) {
            int r = i >> 5;            // 0..127
            int kk = i & (KC2 - 1);    // 0..31
            int row = row0 + r;
            float v = (row < NN) ? h[row * IND + k0 + kk] : 0.f;
            hsT[kk * HSTR2 + r] = v;
        }
        __syncthreads();

        const float* hp = &hsT[8 * ty];
        const float4* wq = reinterpret_cast<const float4*>(Wc) + tx;
#pragma unroll 8
        for (int kk = 0; kk < KC2; kk++) {
            float4 a0 = *reinterpret_cast<const float4*>(hp);      // LDS.128
            float4 a1 = *reinterpret_cast<const float4*>(hp + 4);  // LDS.128
            hp += HSTR2;
            float4 w = wq[kk * (HD / 4)];                          // LDS.128
            acc[0][0] = fmaf(a0.x, w.x, acc[0][0]);
            acc[0][1] = fmaf(a0.x, w.y, acc[0][1]);
            acc[0][2] = fmaf(a0.x, w.z, acc[0][2]);
            acc[0][3] = fmaf(a0.x, w.w, acc[0][3]);
            acc[1][0] = fmaf(a0.y, w.x, acc[1][0]);
            acc[1][1] = fmaf(a0.y, w.y, acc[1][1]);
            acc[1][2] = fmaf(a0.y, w.z, acc[1][2]);
            acc[1][3] = fmaf(a0.y, w.w, acc[1][3]);
            acc[2][0] = fmaf(a0.z, w.x, acc[2][0]);
            acc[2][1] = fmaf(a0.z, w.y, acc[2][1]);
            acc[2][2] = fmaf(a0.z, w.z, acc[2][2]);
            acc[2][3] = fmaf(a0.z, w.w, acc[2][3]);
            acc[3][0] = fmaf(a0.w, w.x, acc[3][0]);
            acc[3][1] = fmaf(a0.w, w.y, acc[3][1]);
            acc[3][2] = fmaf(a0.w, w.z, acc[3][2]);
            acc[3][3] = fmaf(a0.w, w.w, acc[3][3]);
            acc[4][0] = fmaf(a1.x, w.x, acc[4][0]);
            acc[4][1] = fmaf(a1.x, w.y, acc[4][1]);
            acc[4][2] = fmaf(a1.x, w.z, acc[4][2]);
            acc[4][3] = fmaf(a1.x, w.w, acc[4][3]);
            acc[5][0] = fmaf(a1.y, w.x, acc[5][0]);
            acc[5][1] = fmaf(a1.y, w.y, acc[5][1]);
            acc[5][2] = fmaf(a1.y, w.z, acc[5][2]);
            acc[5][3] = fmaf(a1.y, w.w, acc[5][3]);
            acc[6][0] = fmaf(a1.z, w.x, acc[6][0]);
            acc[6][1] = fmaf(a1.z, w.y, acc[6][1]);
            acc[6][2] = fmaf(a1.z, w.z, acc[6][2]);
            acc[6][3] = fmaf(a1.z, w.w, acc[6][3]);
            acc[7][0] = fmaf(a1.w, w.x, acc[7][0]);
            acc[7][1] = fmaf(a1.w, w.y, acc[7][1]);
            acc[7][2] = fmaf(a1.w, w.z, acc[7][2]);
            acc[7][3] = fmaf(a1.w, w.w, acc[7][3]);
        }
    }

#pragma unroll
    for (int j = 0; j < 8; j++) {
        int row = row0 + 8 * ty + j;
        if (row < NN) {
            float s = g_norm_src[row];
            float4 o = make_float4(acc[j][0] * s, acc[j][1] * s,
                                   acc[j][2] * s, acc[j][3] * s);
            reinterpret_cast<float4*>(g_x1)[row * (HD / 4) + tx] = o;
        }
    }
}

// ============================================================================
// GEMM2: g_x2 = (elu(agg1*norm_dst + b1) * norm_src) @ W2  [100000x64 @ 64x64]
// Same 128x64 / 8x4 structure; layer-1 epilogue (norm+bias+ELU+norm) fused
// into the staging pass. K=64 in 2 chunks of 32.
// ============================================================================
__global__ __launch_bounds__(256) void k_gemm2(const float* __restrict__ b1,
                                               const float* __restrict__ W2) {
    __shared__ __align__(16) float Wc[HD * HD];        // 16 KB (all of W2)
    __shared__ __align__(16) float tsT[KC2 * HSTR2];   // 16.5 KB
    __shared__ float b1s[HD];
    int tid = threadIdx.x;
    int ty = tid >> 4;
    int tx = tid & 15;
    int row0 = blockIdx.x * 128;

    for (int i = tid; i < HD * HD; i += 256) Wc[i] = W2[i];
    if (tid < HD) b1s[tid] = b1[tid];

    float acc[8][4];
#pragma unroll
    for (int j = 0; j < 8; j++)
#pragma unroll
        for (int c = 0; c < 4; c++) acc[j][c] = 0.f;

#pragma unroll 1
    for (int kc = 0; kc < HD / KC2; kc++) {
        int k0 = kc * KC2;
        __syncthreads();
        // stage + fused layer-1 epilogue, transposed
        for (int i = tid; i < 128 * KC2; i += 256) {
            int r = i >> 5;
            int kk = i & (KC2 - 1);
            int row = row0 + r;
            float v = 0.f;
            if (row < NN) {
                int k = k0 + kk;
                v = g_agg1[row * HD + k] * g_norm_dst[row] + b1s[k];
                v = (v > 0.f) ? v : expm1f(v);
                v *= g_norm_src[row];
            }
            tsT[kk * HSTR2 + r] = v;
        }
        __syncthreads();

        const float* tp = &tsT[8 * ty];
        const float4* wq = reinterpret_cast<const float4*>(Wc + k0 * HD) + tx;
#pragma unroll 8
        for (int kk = 0; kk < KC2; kk++) {
            float4 a0 = *reinterpret_cast<const float4*>(tp);
            float4 a1 = *reinterpret_cast<const float4*>(tp + 4);
            tp += HSTR2;
            float4 w = wq[kk * (HD / 4)];
            acc[0][0] = fmaf(a0.x, w.x, acc[0][0]);
            acc[0][1] = fmaf(a0.x, w.y, acc[0][1]);
            acc[0][2] = fmaf(a0.x, w.z, acc[0][2]);
            acc[0][3] = fmaf(a0.x, w.w, acc[0][3]);
            acc[1][0] = fmaf(a0.y, w.x, acc[1][0]);
            acc[1][1] = fmaf(a0.y, w.y, acc[1][1]);
            acc[1][2] = fmaf(a0.y, w.z, acc[1][2]);
            acc[1][3] = fmaf(a0.y, w.w, acc[1][3]);
            acc[2][0] = fmaf(a0.z, w.x, acc[2][0]);
            acc[2][1] = fmaf(a0.z, w.y, acc[2][1]);
            acc[2][2] = fmaf(a0.z, w.z, acc[2][2]);
            acc[2][3] = fmaf(a0.z, w.w, acc[2][3]);
            acc[3][0] = fmaf(a0.w, w.x, acc[3][0]);
            acc[3][1] = fmaf(a0.w, w.y, acc[3][1]);
            acc[3][2] = fmaf(a0.w, w.z, acc[3][2]);
            acc[3][3] = fmaf(a0.w, w.w, acc[3][3]);
            acc[4][0] = fmaf(a1.x, w.x, acc[4][0]);
            acc[4][1] = fmaf(a1.x, w.y, acc[4][1]);
            acc[4][2] = fmaf(a1.x, w.z, acc[4][2]);
            acc[4][3] = fmaf(a1.x, w.w, acc[4][3]);
            acc[5][0] = fmaf(a1.y, w.x, acc[5][0]);
            acc[5][1] = fmaf(a1.y, w.y, acc[5][1]);
            acc[5][2] = fmaf(a1.y, w.z, acc[5][2]);
            acc[5][3] = fmaf(a1.y, w.w, acc[5][3]);
            acc[6][0] = fmaf(a1.z, w.x, acc[6][0]);
            acc[6][1] = fmaf(a1.z, w.y, acc[6][1]);
            acc[6][2] = fmaf(a1.z, w.z, acc[6][2]);
            acc[6][3] = fmaf(a1.z, w.w, acc[6][3]);
            acc[7][0] = fmaf(a1.w, w.x, acc[7][0]);
            acc[7][1] = fmaf(a1.w, w.y, acc[7][1]);
            acc[7][2] = fmaf(a1.w, w.z, acc[7][2]);
            acc[7][3] = fmaf(a1.w, w.w, acc[7][3]);
        }
    }

#pragma unroll
    for (int j = 0; j < 8; j++) {
        int row = row0 + 8 * ty + j;
        if (row < NN) {
            float4 o = make_float4(acc[j][0], acc[j][1], acc[j][2], acc[j][3]);
            reinterpret_cast<float4*>(g_x2)[row * (HD / 4) + tx] = o;
        }
    }
}

// ============================================================================
// CSR aggregation: warp per node, lane owns float2 of the 64-wide row.
// Vectorized int4 index loads + 8-deep gather unroll. No atomics.
// ============================================================================
__device__ __forceinline__ float2 agg_row(const float2* __restrict__ x2,
                                          int n, int lane) {
    int start = g_start[n];
    int end = start + g_deg_in[n];
    float2 acc = make_float2(0.f, 0.f);
    int e = start;
    // scalar prologue to 16B-align the index pointer (uniform across warp)
    int ealign = (start + 3) & ~3;
    if (ealign > end) ealign = end;
    for (; e < ealign; e++) {
        int s = __ldg(&g_esrc[e]);
        float2 v = __ldg(&x2[s * 32 + lane]);
        acc.x += v.x;
        acc.y += v.y;
    }
    for (; e + 8 <= end; e += 8) {
        int4 sa = *reinterpret_cast<const int4*>(&g_esrc[e]);
        int4 sb = *reinterpret_cast<const int4*>(&g_esrc[e + 4]);
        float2 v0 = __ldg(&x2[sa.x * 32 + lane]);
        float2 v1 = __ldg(&x2[sa.y * 32 + lane]);
        float2 v2 = __ldg(&x2[sa.z * 32 + lane]);
        float2 v3 = __ldg(&x2[sa.w * 32 + lane]);
        float2 v4 = __ldg(&x2[sb.x * 32 + lane]);
        float2 v5 = __ldg(&x2[sb.y * 32 + lane]);
        float2 v6 = __ldg(&x2[sb.z * 32 + lane]);
        float2 v7 = __ldg(&x2[sb.w * 32 + lane]);
        acc.x += (v0.x + v1.x) + (v2.x + v3.x) + (v4.x + v5.x) + (v6.x + v7.x);
        acc.y += (v0.y + v1.y) + (v2.y + v3.y) + (v4.y + v5.y) + (v6.y + v7.y);
    }
    if (e + 4 <= end) {
        int4 sa = *reinterpret_cast<const int4*>(&g_esrc[e]);
        float2 v0 = __ldg(&x2[sa.x * 32 + lane]);
        float2 v1 = __ldg(&x2[sa.y * 32 + lane]);
        float2 v2 = __ldg(&x2[sa.z * 32 + lane]);
        float2 v3 = __ldg(&x2[sa.w * 32 + lane]);
        acc.x += (v0.x + v1.x) + (v2.x + v3.x);
        acc.y += (v0.y + v1.y) + (v2.y + v3.y);
        e += 4;
    }
    for (; e < end; e++) {
        int s = __ldg(&g_esrc[e]);
        float2 v = __ldg(&x2[s * 32 + lane]);
        acc.x += v.x;
        acc.y += v.y;
    }
    return acc;
}

__global__ __launch_bounds__(256) void k_agg1() {
    int n = (blockIdx.x * 256 + threadIdx.x) >> 5;
    int lane = threadIdx.x & 31;
    if (n >= NN) return;
    float2 acc = agg_row(reinterpret_cast<const float2*>(g_x1), n, lane);
    reinterpret_cast<float2*>(g_agg1)[n * 32 + lane] = acc;
}

// layer-2 aggregation with fused finalize: out = agg*norm_dst + b2
__global__ __launch_bounds__(256) void k_agg2(float* __restrict__ out,
                                              const float* __restrict__ b2) {
    int n = (blockIdx.x * 256 + threadIdx.x) >> 5;
    int lane = threadIdx.x & 31;
    if (n >= NN) return;
    float2 acc = agg_row(reinterpret_cast<const float2*>(g_x2), n, lane);
    float nd = g_norm_dst[n];
    float2 bb = __ldg(reinterpret_cast<const float2*>(b2) + lane);
    float2 o = make_float2(acc.x * nd + bb.x, acc.y * nd + bb.y);
    reinterpret_cast<float2*>(out)[n * 32 + lane] = o;
}

extern "C" void kernel_launch(void* const* d_in, const int* in_sizes, int n_in,
                              void* d_out, int out_size) {
    const float* h   = (const float*)d_in[0];
    const int*   src = (const int*)d_in[1];
    const int*   dst = (const int*)d_in[2];
    const float* W1  = (const float*)d_in[3];
    const float* b1  = (const float*)d_in[4];
    const float* W2  = (const float*)d_in[5];
    const float* b2  = (const float*)d_in[6];
    float* out = (float*)d_out;

    const int GBLK = (NN + 127) / 128;           // 782
    const int AGG_BLK = (NN * 32 + 255) / 256;   // warp per node

    // ---- graph preprocessing (CSR by dst) ----
    k_init<<<(NN + 255) / 256, 256>>>();
    k_deg<<<(NE + 255) / 256, 256>>>(src, dst);
    k_scan1<<<SCAN_BLOCKS, 256>>>();
    k_scan2<<<1, 512>>>();
    k_scan3<<<(NN + 255) / 256, 256>>>();        // scan finalize + norms
    k_place<<<(NE + 255) / 256, 256>>>(src, dst);

    // ---- layer 1 ----
    k_gemm1<<<GBLK, 256>>>(h, W1);
    k_agg1<<<AGG_BLK, 256>>>();

    // ---- layer 2 (layer-1 epilogue fused into gemm2; finalize fused into agg2) ----
    k_gemm2<<<GBLK, 256>>>(b1, W2);
    k_agg2<<<AGG_BLK, 256>>>(out, b2);
}

// round 8
// speedup vs baseline: 1.1410x; 1.1410x over previous
#include <cuda_runtime.h>
#include <cstdint>

#define NN 100000
#define NE 1600000
#define IND 128
#define HD 64
#define SCAN_BLOCKS 391   // ceil(NN/256)

// -------- scratch (no allocation allowed: __device__ globals) --------
__device__ int   g_deg_out[NN];
__device__ int   g_deg_in[NN];
__device__ int   g_start[NN];     // CSR row start (exclusive scan of deg_in)
__device__ int   g_cursor[NN];    // placement cursors
__device__ int   g_bsum[SCAN_BLOCKS];
__device__ __align__(16) int g_esrc[NE];   // edge sources grouped by dst
__device__ float g_norm_src[NN];
__device__ float g_norm_dst[NN];
__device__ __align__(16) float g_x1[NN * HD];   // projected layer-1 features
__device__ __align__(16) float g_agg1[NN * HD]; // layer-1 aggregation
__device__ __align__(16) float g_x2[NN * HD];   // projected layer-2 features

// -------- init: zero integer degree counters --------
__global__ void k_init() {
    int i = blockIdx.x * blockDim.x + threadIdx.x;
    if (i < NN) {
        g_deg_out[i] = 0;
        g_deg_in[i] = 0;
    }
}

// -------- integer degree histograms --------
__global__ void k_deg(const int* __restrict__ src, const int* __restrict__ dst) {
    int i = blockIdx.x * blockDim.x + threadIdx.x;
    if (i < NE) {
        atomicAdd(&g_deg_out[src[i]], 1);
        atomicAdd(&g_deg_in[dst[i]], 1);
    }
}

// -------- exclusive scan of deg_in -> g_start (3 kernels) --------
__global__ void k_scan1() {
    __shared__ int s[256];
    int tid = threadIdx.x;
    int i = blockIdx.x * 256 + tid;
    int v = (i < NN) ? g_deg_in[i] : 0;
    s[tid] = v;
    __syncthreads();
    for (int off = 1; off < 256; off <<= 1) {
        int t = (tid >= off) ? s[tid - off] : 0;
        __syncthreads();
        s[tid] += t;
        __syncthreads();
    }
    if (i < NN) g_start[i] = s[tid] - v;          // block-local exclusive
    if (tid == 255) g_bsum[blockIdx.x] = s[255];  // block total
}

__global__ void k_scan2() {  // single block of 512: exclusive scan of block sums
    __shared__ int s[512];
    int tid = threadIdx.x;
    int v = (tid < SCAN_BLOCKS) ? g_bsum[tid] : 0;
    s[tid] = v;
    __syncthreads();
    for (int off = 1; off < 512; off <<= 1) {
        int t = (tid >= off) ? s[tid - off] : 0;
        __syncthreads();
        s[tid] += t;
        __syncthreads();
    }
    if (tid < SCAN_BLOCKS) g_bsum[tid] = s[tid] - v;  // exclusive
}

// scan finalize + norms (fused)
__global__ void k_scan3() {
    int i = blockIdx.x * blockDim.x + threadIdx.x;
    if (i < NN) {
        int st = g_start[i] + g_bsum[i >> 8];
        g_start[i] = st;
        g_cursor[i] = st;
        g_norm_src[i] = rsqrtf(fmaxf((float)g_deg_out[i], 1.f));
        g_norm_dst[i] = rsqrtf(fmaxf((float)g_deg_in[i], 1.f));
    }
}

// -------- CSR placement: group edge sources by dst --------
__global__ void k_place(const int* __restrict__ src, const int* __restrict__ dst) {
    int i = blockIdx.x * blockDim.x + threadIdx.x;
    if (i < NE) {
        int d = dst[i];
        int pos = atomicAdd(&g_cursor[d], 1);
        g_esrc[pos] = src[i];
    }
}

// ============================================================================
// TF32 tensor-core GEMM helpers (mma.sync m16n8k8)
// ============================================================================
__device__ __forceinline__ uint32_t f2tf32(float f) {
    uint32_t r;
    asm("cvt.rna.tf32.f32 %0, %1;" : "=r"(r) : "f"(f));
    return r;
}

__device__ __forceinline__ void mma_tf32(float c[4],
                                         uint32_t a0, uint32_t a1,
                                         uint32_t a2, uint32_t a3,
                                         uint32_t b0, uint32_t b1) {
    asm volatile(
        "mma.sync.aligned.m16n8k8.row.col.f32.tf32.tf32.f32 "
        "{%0,%1,%2,%3}, {%4,%5,%6,%7}, {%8,%9}, {%0,%1,%2,%3};"
        : "+f"(c[0]), "+f"(c[1]), "+f"(c[2]), "+f"(c[3])
        : "r"(a0), "r"(a1), "r"(a2), "r"(a3), "r"(b0), "r"(b1));
}

#define ASTR 36   // A smem row stride: banks 4q+c -> conflict-free fragments
#define BSTR 72   // B smem row stride: banks 8c+q -> conflict-free fragments
#define KCHUNK 32

// ============================================================================
// GEMM1: g_x1 = ((h @ W1) * norm_src)   [100000x128 @ 128x64]
// 128x64 tile per block, 8 warps, warp w owns rows [16w,16w+16), all 64 cols.
// K in chunks of 32 (4 mma k-steps). C frags: float[8][4] per thread.
// ============================================================================
__global__ __launch_bounds__(256) void k_gemm1(const float* __restrict__ h,
                                               const float* __restrict__ W1) {
    __shared__ uint32_t As[128 * ASTR];     // 18.4 KB  [r][kk]
    __shared__ uint32_t Bs[KCHUNK * BSTR];  // 9.2 KB   [kk][n]
    int tid = threadIdx.x;
    int w = tid >> 5;
    int lane = tid & 31;
    int q = lane >> 2;       // groupID 0..7
    int cc = lane & 3;       // threadID-in-group 0..3
    int row0 = blockIdx.x * 128;

    float c[8][4];
#pragma unroll
    for (int nt = 0; nt < 8; nt++)
#pragma unroll
        for (int j = 0; j < 4; j++) c[nt][j] = 0.f;

#pragma unroll 1
    for (int kc = 0; kc < IND / KCHUNK; kc++) {
        int k0 = kc * KCHUNK;
        __syncthreads();
        // stage W chunk [32][64]
        for (int i = tid; i < KCHUNK * HD; i += 256) {
            int kk = i >> 6, n = i & 63;
            Bs[kk * BSTR + n] = f2tf32(W1[(k0 + kk) * HD + n]);
        }
        // stage A chunk [128][32] (coalesced gmem: warp reads 32 consecutive k)
        for (int i = tid; i < 128 * KCHUNK; i += 256) {
            int r = i >> 5, kk = i & 31;
            int row = row0 + r;
            float v = (row < NN) ? h[row * IND + k0 + kk] : 0.f;
            As[r * ASTR + kk] = f2tf32(v);
        }
        __syncthreads();

        const uint32_t* ap = As + (w * 16 + q) * ASTR + cc;
#pragma unroll
        for (int ks = 0; ks < 4; ks++) {
            uint32_t a0 = ap[ks * 8];
            uint32_t a1 = ap[8 * ASTR + ks * 8];
            uint32_t a2 = ap[ks * 8 + 4];
            uint32_t a3 = ap[8 * ASTR + ks * 8 + 4];
            const uint32_t* bp = Bs + (ks * 8 + cc) * BSTR + q;
#pragma unroll
            for (int nt = 0; nt < 8; nt++) {
                uint32_t b0 = bp[nt * 8];
                uint32_t b1 = bp[4 * BSTR + nt * 8];
                mma_tf32(c[nt], a0, a1, a2, a3, b0, b1);
            }
        }
    }

    // epilogue: scale by norm_src, store float2 (cols 2cc, 2cc+1 contiguous)
    int r0g = row0 + w * 16 + q;
    int r1g = r0g + 8;
    float ns0 = (r0g < NN) ? g_norm_src[r0g] : 0.f;
    float ns1 = (r1g < NN) ? g_norm_src[r1g] : 0.f;
#pragma unroll
    for (int nt = 0; nt < 8; nt++) {
        int col = nt * 8 + cc * 2;
        if (r0g < NN) {
            float2 o = make_float2(c[nt][0] * ns0, c[nt][1] * ns0);
            *reinterpret_cast<float2*>(&g_x1[r0g * HD + col]) = o;
        }
        if (r1g < NN) {
            float2 o = make_float2(c[nt][2] * ns1, c[nt][3] * ns1);
            *reinterpret_cast<float2*>(&g_x1[r1g * HD + col]) = o;
        }
    }
}

// ============================================================================
// GEMM2: g_x2 = (elu(agg1*norm_dst + b1) * norm_src) @ W2  [100000x64 @ 64x64]
// Same structure; layer-1 epilogue fused into A staging. K=64 (2 chunks).
// ============================================================================
__global__ __launch_bounds__(256) void k_gemm2(const float* __restrict__ b1,
                                               const float* __restrict__ W2) {
    __shared__ uint32_t As[128 * ASTR];
    __shared__ uint32_t Bs[KCHUNK * BSTR];
    __shared__ float b1s[HD];
    int tid = threadIdx.x;
    int w = tid >> 5;
    int lane = tid & 31;
    int q = lane >> 2;
    int cc = lane & 3;
    int row0 = blockIdx.x * 128;

    if (tid < HD) b1s[tid] = b1[tid];

    float c[8][4];
#pragma unroll
    for (int nt = 0; nt < 8; nt++)
#pragma unroll
        for (int j = 0; j < 4; j++) c[nt][j] = 0.f;

#pragma unroll 1
    for (int kc = 0; kc < HD / KCHUNK; kc++) {
        int k0 = kc * KCHUNK;
        __syncthreads();
        for (int i = tid; i < KCHUNK * HD; i += 256) {
            int kk = i >> 6, n = i & 63;
            Bs[kk * BSTR + n] = f2tf32(W2[(k0 + kk) * HD + n]);
        }
        // stage A with fused layer-1 epilogue (norm, bias, ELU, norm)
        for (int i = tid; i < 128 * KCHUNK; i += 256) {
            int r = i >> 5, kk = i & 31;
            int row = row0 + r;
            float v = 0.f;
            if (row < NN) {
                int k = k0 + kk;
                v = g_agg1[row * HD + k] * g_norm_dst[row] + b1s[k];
                v = (v > 0.f) ? v : expm1f(v);
                v *= g_norm_src[row];
            }
            As[r * ASTR + kk] = f2tf32(v);
        }
        __syncthreads();

        const uint32_t* ap = As + (w * 16 + q) * ASTR + cc;
#pragma unroll
        for (int ks = 0; ks < 4; ks++) {
            uint32_t a0 = ap[ks * 8];
            uint32_t a1 = ap[8 * ASTR + ks * 8];
            uint32_t a2 = ap[ks * 8 + 4];
            uint32_t a3 = ap[8 * ASTR + ks * 8 + 4];
            const uint32_t* bp = Bs + (ks * 8 + cc) * BSTR + q;
#pragma unroll
            for (int nt = 0; nt < 8; nt++) {
                uint32_t b0 = bp[nt * 8];
                uint32_t b1r = bp[4 * BSTR + nt * 8];
                mma_tf32(c[nt], a0, a1, a2, a3, b0, b1r);
            }
        }
    }

    int r0g = row0 + w * 16 + q;
    int r1g = r0g + 8;
#pragma unroll
    for (int nt = 0; nt < 8; nt++) {
        int col = nt * 8 + cc * 2;
        if (r0g < NN) {
            float2 o = make_float2(c[nt][0], c[nt][1]);
            *reinterpret_cast<float2*>(&g_x2[r0g * HD + col]) = o;
        }
        if (r1g < NN) {
            float2 o = make_float2(c[nt][2], c[nt][3]);
            *reinterpret_cast<float2*>(&g_x2[r1g * HD + col]) = o;
        }
    }
}

// ============================================================================
// CSR aggregation: warp per node, lane owns float2 of the 64-wide row.
// agg[n] = sum over in-edges of x[src]; no atomics.
// ============================================================================
__device__ __forceinline__ float2 agg_row(const float2* __restrict__ x2,
                                          int n, int lane) {
    int start = g_start[n];
    int end = start + g_deg_in[n];
    float2 acc = make_float2(0.f, 0.f);
    int e = start;
    for (; e + 4 <= end; e += 4) {
        int s0 = __ldg(&g_esrc[e]);
        int s1 = __ldg(&g_esrc[e + 1]);
        int s2 = __ldg(&g_esrc[e + 2]);
        int s3 = __ldg(&g_esrc[e + 3]);
        float2 v0 = __ldg(&x2[s0 * 32 + lane]);
        float2 v1 = __ldg(&x2[s1 * 32 + lane]);
        float2 v2 = __ldg(&x2[s2 * 32 + lane]);
        float2 v3 = __ldg(&x2[s3 * 32 + lane]);
        acc.x += (v0.x + v1.x) + (v2.x + v3.x);
        acc.y += (v0.y + v1.y) + (v2.y + v3.y);
    }
    for (; e < end; e++) {
        int s = __ldg(&g_esrc[e]);
        float2 v = __ldg(&x2[s * 32 + lane]);
        acc.x += v.x;
        acc.y += v.y;
    }
    return acc;
}

__global__ __launch_bounds__(256) void k_agg1() {
    int n = (blockIdx.x * 256 + threadIdx.x) >> 5;
    int lane = threadIdx.x & 31;
    if (n >= NN) return;
    float2 acc = agg_row(reinterpret_cast<const float2*>(g_x1), n, lane);
    reinterpret_cast<float2*>(g_agg1)[n * 32 + lane] = acc;
}

// layer-2 aggregation with fused finalize: out = agg*norm_dst + b2
__global__ __launch_bounds__(256) void k_agg2(float* __restrict__ out,
                                              const float* __restrict__ b2) {
    int n = (blockIdx.x * 256 + threadIdx.x) >> 5;
    int lane = threadIdx.x & 31;
    if (n >= NN) return;
    float2 acc = agg_row(reinterpret_cast<const float2*>(g_x2), n, lane);
    float nd = g_norm_dst[n];
    float2 bb = __ldg(reinterpret_cast<const float2*>(b2) + lane);
    float2 o = make_float2(acc.x * nd + bb.x, acc.y * nd + bb.y);
    reinterpret_cast<float2*>(out)[n * 32 + lane] = o;
}

extern "C" void kernel_launch(void* const* d_in, const int* in_sizes, int n_in,
                              void* d_out, int out_size) {
    const float* h   = (const float*)d_in[0];
    const int*   src = (const int*)d_in[1];
    const int*   dst = (const int*)d_in[2];
    const float* W1  = (const float*)d_in[3];
    const float* b1  = (const float*)d_in[4];
    const float* W2  = (const float*)d_in[5];
    const float* b2  = (const float*)d_in[6];
    float* out = (float*)d_out;

    const int GBLK = (NN + 127) / 128;           // 782
    const int AGG_BLK = (NN * 32 + 255) / 256;   // warp per node

    // ---- graph preprocessing (CSR by dst) ----
    k_init<<<(NN + 255) / 256, 256>>>();
    k_deg<<<(NE + 255) / 256, 256>>>(src, dst);
    k_scan1<<<SCAN_BLOCKS, 256>>>();
    k_scan2<<<1, 512>>>();
    k_scan3<<<(NN + 255) / 256, 256>>>();        // scan finalize + norms
    k_place<<<(NE + 255) / 256, 256>>>(src, dst);

    // ---- layer 1 ----
    k_gemm1<<<GBLK, 256>>>(h, W1);
    k_agg1<<<AGG_BLK, 256>>>();

    // ---- layer 2 (layer-1 epilogue fused into gemm2; finalize fused into agg2) ----
    k_gemm2<<<GBLK, 256>>>(b1, W2);
    k_agg2<<<AGG_BLK, 256>>>(out, b2);
}

// round 9
// speedup vs baseline: 1.1910x; 1.0438x over previous
#include <cuda_runtime.h>
#include <cuda_fp16.h>
#include <cstdint>

#define NN 100000
#define NE 1600000
#define IND 128
#define HD 64
#define SCAN_BLOCKS 391   // ceil(NN/256)

// -------- scratch (no allocation allowed: __device__ globals) --------
__device__ int   g_deg_out[NN];
__device__ int   g_deg_in[NN];
__device__ int   g_start[NN];     // CSR row start (exclusive scan of deg_in)
__device__ int   g_cursor[NN];    // placement cursors
__device__ int   g_bsum[SCAN_BLOCKS];
__device__ __align__(16) int g_esrc[NE];   // edge sources grouped by dst
__device__ float g_norm_src[NN];
__device__ float g_norm_dst[NN];
__device__ __align__(16) __half2 g_x1h[NN * 32];  // projected layer-1 feats (fp16)
__device__ __align__(16) float   g_agg1[NN * HD]; // layer-1 aggregation (fp32)
__device__ __align__(16) __half2 g_x2h[NN * 32];  // projected layer-2 feats (fp16)

// -------- init: zero integer degree counters --------
__global__ void k_init() {
    int i = blockIdx.x * blockDim.x + threadIdx.x;
    if (i < NN) {
        g_deg_out[i] = 0;
        g_deg_in[i] = 0;
    }
}

// -------- integer degree histograms --------
__global__ void k_deg(const int* __restrict__ src, const int* __restrict__ dst) {
    int i = blockIdx.x * blockDim.x + threadIdx.x;
    if (i < NE) {
        atomicAdd(&g_deg_out[src[i]], 1);
        atomicAdd(&g_deg_in[dst[i]], 1);
    }
}

// -------- exclusive scan of deg_in -> g_start --------
__global__ void k_scan1() {
    __shared__ int s[256];
    int tid = threadIdx.x;
    int i = blockIdx.x * 256 + tid;
    int v = (i < NN) ? g_deg_in[i] : 0;
    s[tid] = v;
    __syncthreads();
    for (int off = 1; off < 256; off <<= 1) {
        int t = (tid >= off) ? s[tid - off] : 0;
        __syncthreads();
        s[tid] += t;
        __syncthreads();
    }
    if (i < NN) g_start[i] = s[tid] - v;          // block-local exclusive
    if (tid == 255) g_bsum[blockIdx.x] = s[255];  // block total
}

// single block of 512: shfl-based exclusive scan of block sums
__global__ void k_scan2() {
    __shared__ int warp_tot[16];
    int tid = threadIdx.x;
    int lane = tid & 31;
    int wid = tid >> 5;
    int v = (tid < SCAN_BLOCKS) ? g_bsum[tid] : 0;
    int x = v;
#pragma unroll
    for (int off = 1; off < 32; off <<= 1) {
        int t = __shfl_up_sync(0xffffffffu, x, off);
        if (lane >= off) x += t;
    }
    if (lane == 31) warp_tot[wid] = x;
    __syncthreads();
    if (wid == 0) {
        int w = (lane < 16) ? warp_tot[lane] : 0;
#pragma unroll
        for (int off = 1; off < 16; off <<= 1) {
            int t = __shfl_up_sync(0xffffffffu, w, off);
            if (lane >= off) w += t;
        }
        if (lane < 16) warp_tot[lane] = w;
    }
    __syncthreads();
    int base = (wid > 0) ? warp_tot[wid - 1] : 0;
    if (tid < SCAN_BLOCKS) g_bsum[tid] = base + x - v;  // exclusive
}

// scan finalize + norms (fused)
__global__ void k_scan3() {
    int i = blockIdx.x * blockDim.x + threadIdx.x;
    if (i < NN) {
        int st = g_start[i] + g_bsum[i >> 8];
        g_start[i] = st;
        g_cursor[i] = st;
        g_norm_src[i] = rsqrtf(fmaxf((float)g_deg_out[i], 1.f));
        g_norm_dst[i] = rsqrtf(fmaxf((float)g_deg_in[i], 1.f));
    }
}

// -------- CSR placement: group edge sources by dst --------
__global__ void k_place(const int* __restrict__ src, const int* __restrict__ dst) {
    int i = blockIdx.x * blockDim.x + threadIdx.x;
    if (i < NE) {
        int d = dst[i];
        int pos = atomicAdd(&g_cursor[d], 1);
        g_esrc[pos] = src[i];
    }
}

// ============================================================================
// TF32 tensor-core GEMM helpers (mma.sync m16n8k8)
// ============================================================================
__device__ __forceinline__ uint32_t f2tf32(float f) {
    uint32_t r;
    asm("cvt.rna.tf32.f32 %0, %1;" : "=r"(r) : "f"(f));
    return r;
}

__device__ __forceinline__ void mma_tf32(float c[4],
                                         uint32_t a0, uint32_t a1,
                                         uint32_t a2, uint32_t a3,
                                         uint32_t b0, uint32_t b1) {
    asm volatile(
        "mma.sync.aligned.m16n8k8.row.col.f32.tf32.tf32.f32 "
        "{%0,%1,%2,%3}, {%4,%5,%6,%7}, {%8,%9}, {%0,%1,%2,%3};"
        : "+f"(c[0]), "+f"(c[1]), "+f"(c[2]), "+f"(c[3])
        : "r"(a0), "r"(a1), "r"(a2), "r"(a3), "r"(b0), "r"(b1));
}

#define ASTR 36   // A smem row stride: conflict-free fragment loads
#define BSTR 72   // B smem row stride: conflict-free fragment loads
#define KCHUNK 32

// ============================================================================
// GEMM1: x1 = ((h @ W1) * norm_src)  [100000x128 @ 128x64] -> fp16 store
// ============================================================================
__global__ __launch_bounds__(256) void k_gemm1(const float* __restrict__ h,
                                               const float* __restrict__ W1) {
    __shared__ uint32_t As[128 * ASTR];
    __shared__ uint32_t Bs[KCHUNK * BSTR];
    int tid = threadIdx.x;
    int w = tid >> 5;
    int lane = tid & 31;
    int q = lane >> 2;
    int cc = lane & 3;
    int row0 = blockIdx.x * 128;

    float c[8][4];
#pragma unroll
    for (int nt = 0; nt < 8; nt++)
#pragma unroll
        for (int j = 0; j < 4; j++) c[nt][j] = 0.f;

#pragma unroll 1
    for (int kc = 0; kc < IND / KCHUNK; kc++) {
        int k0 = kc * KCHUNK;
        __syncthreads();
        for (int i = tid; i < KCHUNK * HD; i += 256) {
            int kk = i >> 6, n = i & 63;
            Bs[kk * BSTR + n] = f2tf32(W1[(k0 + kk) * HD + n]);
        }
        for (int i = tid; i < 128 * KCHUNK; i += 256) {
            int r = i >> 5, kk = i & 31;
            int row = row0 + r;
            float v = (row < NN) ? h[row * IND + k0 + kk] : 0.f;
            As[r * ASTR + kk] = f2tf32(v);
        }
        __syncthreads();

        const uint32_t* ap = As + (w * 16 + q) * ASTR + cc;
#pragma unroll
        for (int ks = 0; ks < 4; ks++) {
            uint32_t a0 = ap[ks * 8];
            uint32_t a1 = ap[8 * ASTR + ks * 8];
            uint32_t a2 = ap[ks * 8 + 4];
            uint32_t a3 = ap[8 * ASTR + ks * 8 + 4];
            const uint32_t* bp = Bs + (ks * 8 + cc) * BSTR + q;
#pragma unroll
            for (int nt = 0; nt < 8; nt++) {
                uint32_t b0 = bp[nt * 8];
                uint32_t b1 = bp[4 * BSTR + nt * 8];
                mma_tf32(c[nt], a0, a1, a2, a3, b0, b1);
            }
        }
    }

    // epilogue: scale by norm_src, convert to half2, store (4B per frag-pair)
    int r0g = row0 + w * 16 + q;
    int r1g = r0g + 8;
    float ns0 = (r0g < NN) ? g_norm_src[r0g] : 0.f;
    float ns1 = (r1g < NN) ? g_norm_src[r1g] : 0.f;
#pragma unroll
    for (int nt = 0; nt < 8; nt++) {
        int h2col = nt * 4 + cc;   // half2 index = (nt*8 + cc*2)/2
        if (r0g < NN)
            g_x1h[r0g * 32 + h2col] = __floats2half2_rn(c[nt][0] * ns0, c[nt][1] * ns0);
        if (r1g < NN)
            g_x1h[r1g * 32 + h2col] = __floats2half2_rn(c[nt][2] * ns1, c[nt][3] * ns1);
    }
}

// ============================================================================
// GEMM2: x2 = (elu(agg1*norm_dst + b1) * norm_src) @ W2 -> fp16 store
// ============================================================================
__global__ __launch_bounds__(256) void k_gemm2(const float* __restrict__ b1,
                                               const float* __restrict__ W2) {
    __shared__ uint32_t As[128 * ASTR];
    __shared__ uint32_t Bs[KCHUNK * BSTR];
    __shared__ float b1s[HD];
    int tid = threadIdx.x;
    int w = tid >> 5;
    int lane = tid & 31;
    int q = lane >> 2;
    int cc = lane & 3;
    int row0 = blockIdx.x * 128;

    if (tid < HD) b1s[tid] = b1[tid];

    float c[8][4];
#pragma unroll
    for (int nt = 0; nt < 8; nt++)
#pragma unroll
        for (int j = 0; j < 4; j++) c[nt][j] = 0.f;

#pragma unroll 1
    for (int kc = 0; kc < HD / KCHUNK; kc++) {
        int k0 = kc * KCHUNK;
        __syncthreads();
        for (int i = tid; i < KCHUNK * HD; i += 256) {
            int kk = i >> 6, n = i & 63;
            Bs[kk * BSTR + n] = f2tf32(W2[(k0 + kk) * HD + n]);
        }
        // stage A with fused layer-1 epilogue (norm, bias, ELU, norm)
        for (int i = tid; i < 128 * KCHUNK; i += 256) {
            int r = i >> 5, kk = i & 31;
            int row = row0 + r;
            float v = 0.f;
            if (row < NN) {
                int k = k0 + kk;
                v = g_agg1[row * HD + k] * g_norm_dst[row] + b1s[k];
                v = (v > 0.f) ? v : expm1f(v);
                v *= g_norm_src[row];
            }
            As[r * ASTR + kk] = f2tf32(v);
        }
        __syncthreads();

        const uint32_t* ap = As + (w * 16 + q) * ASTR + cc;
#pragma unroll
        for (int ks = 0; ks < 4; ks++) {
            uint32_t a0 = ap[ks * 8];
            uint32_t a1 = ap[8 * ASTR + ks * 8];
            uint32_t a2 = ap[ks * 8 + 4];
            uint32_t a3 = ap[8 * ASTR + ks * 8 + 4];
            const uint32_t* bp = Bs + (ks * 8 + cc) * BSTR + q;
#pragma unroll
            for (int nt = 0; nt < 8; nt++) {
                uint32_t b0 = bp[nt * 8];
                uint32_t b1r = bp[4 * BSTR + nt * 8];
                mma_tf32(c[nt], a0, a1, a2, a3, b0, b1r);
            }
        }
    }

    int r0g = row0 + w * 16 + q;
    int r1g = r0g + 8;
#pragma unroll
    for (int nt = 0; nt < 8; nt++) {
        int h2col = nt * 4 + cc;
        if (r0g < NN)
            g_x2h[r0g * 32 + h2col] = __floats2half2_rn(c[nt][0], c[nt][1]);
        if (r1g < NN)
            g_x2h[r1g * 32 + h2col] = __floats2half2_rn(c[nt][2], c[nt][3]);
    }
}

// ============================================================================
// CSR aggregation: warp per node, lane owns one half2 (2 cols) of the row.
// 128B gathered per edge (vs 256B fp32). fp32 accumulation. No atomics.
// ============================================================================
__device__ __forceinline__ float2 agg_row_h(const __half2* __restrict__ xh,
                                            int n, int lane) {
    int start = g_start[n];
    int end = start + g_deg_in[n];
    float2 acc = make_float2(0.f, 0.f);
    int e = start;
    for (; e + 4 <= end; e += 4) {
        int s0 = __ldg(&g_esrc[e]);
        int s1 = __ldg(&g_esrc[e + 1]);
        int s2 = __ldg(&g_esrc[e + 2]);
        int s3 = __ldg(&g_esrc[e + 3]);
        float2 v0 = __half22float2(__ldg(&xh[s0 * 32 + lane]));
        float2 v1 = __half22float2(__ldg(&xh[s1 * 32 + lane]));
        float2 v2 = __half22float2(__ldg(&xh[s2 * 32 + lane]));
        float2 v3 = __half22float2(__ldg(&xh[s3 * 32 + lane]));
        acc.x += (v0.x + v1.x) + (v2.x + v3.x);
        acc.y += (v0.y + v1.y) + (v2.y + v3.y);
    }
    for (; e < end; e++) {
        int s = __ldg(&g_esrc[e]);
        float2 v = __half22float2(__ldg(&xh[s * 32 + lane]));
        acc.x += v.x;
        acc.y += v.y;
    }
    return acc;
}

__global__ __launch_bounds__(256) void k_agg1() {
    int n = (blockIdx.x * 256 + threadIdx.x) >> 5;
    int lane = threadIdx.x & 31;
    if (n >= NN) return;
    float2 acc = agg_row_h(g_x1h, n, lane);
    reinterpret_cast<float2*>(g_agg1)[n * 32 + lane] = acc;
}

// layer-2 aggregation with fused finalize: out = agg*norm_dst + b2
__global__ __launch_bounds__(256) void k_agg2(float* __restrict__ out,
                                              const float* __restrict__ b2) {
    int n = (blockIdx.x * 256 + threadIdx.x) >> 5;
    int lane = threadIdx.x & 31;
    if (n >= NN) return;
    float2 acc = agg_row_h(g_x2h, n, lane);
    float nd = g_norm_dst[n];
    float2 bb = __ldg(reinterpret_cast<const float2*>(b2) + lane);
    float2 o = make_float2(acc.x * nd + bb.x, acc.y * nd + bb.y);
    reinterpret_cast<float2*>(out)[n * 32 + lane] = o;
}

extern "C" void kernel_launch(void* const* d_in, const int* in_sizes, int n_in,
                              void* d_out, int out_size) {
    const float* h   = (const float*)d_in[0];
    const int*   src = (const int*)d_in[1];
    const int*   dst = (const int*)d_in[2];
    const float* W1  = (const float*)d_in[3];
    const float* b1  = (const float*)d_in[4];
    const float* W2  = (const float*)d_in[5];
    const float* b2  = (const float*)d_in[6];
    float* out = (float*)d_out;

    const int GBLK = (NN + 127) / 128;           // 782
    const int AGG_BLK = (NN * 32 + 255) / 256;   // warp per node

    // ---- graph preprocessing (CSR by dst) ----
    k_init<<<(NN + 255) / 256, 256>>>();
    k_deg<<<(NE + 255) / 256, 256>>>(src, dst);
    k_scan1<<<SCAN_BLOCKS, 256>>>();
    k_scan2<<<1, 512>>>();
    k_scan3<<<(NN + 255) / 256, 256>>>();        // scan finalize + norms
    k_place<<<(NE + 255) / 256, 256>>>(src, dst);

    // ---- layer 1 ----
    k_gemm1<<<GBLK, 256>>>(h, W1);
    k_agg1<<<AGG_BLK, 256>>>();

    // ---- layer 2 ----
    k_gemm2<<<GBLK, 256>>>(b1, W2);
    k_agg2<<<AGG_BLK, 256>>>(out, b2);
}

// round 11
// speedup vs baseline: 1.2586x; 1.0568x over previous
#include <cuda_runtime.h>
#include <cuda_fp16.h>
#include <cstdint>

#define NN 100000
#define NE 1600000
#define IND 128
#define HD 64
#define SCAN_BLOCKS 391   // ceil(NN/256)

// -------- scratch (no allocation allowed: __device__ globals) --------
__device__ int   g_deg_out[NN];
__device__ int   g_deg_in[NN];
__device__ int   g_start[NN];     // CSR row start, block-local exclusive
__device__ int   g_cur0[NN];      // relative placement cursors (zeroed)
__device__ int   g_bsum[SCAN_BLOCKS];  // after scan1: exclusive block offsets
__device__ int   g_scan_done;
__device__ __align__(16) int g_esrc[NE];          // edge sources grouped by dst
__device__ __align__(16) __half2 g_x1h[NN * 32];  // layer-1 feats (fp16)
__device__ __align__(16) float   g_agg1[NN * HD]; // layer-1 aggregation (fp32)
__device__ __align__(16) __half2 g_x2h[NN * 32];  // layer-2 feats (fp16)

// -------- init: zero counters --------
__global__ void k_init() {
    int i = blockIdx.x * blockDim.x + threadIdx.x;
    if (i < NN) {
        g_deg_out[i] = 0;
        g_deg_in[i] = 0;
        g_cur0[i] = 0;
    }
    if (i == 0) g_scan_done = 0;
}

// -------- integer degree histograms --------
__global__ void k_deg(const int* __restrict__ src, const int* __restrict__ dst) {
    int i = blockIdx.x * blockDim.x + threadIdx.x;
    if (i < NE) {
        atomicAdd(&g_deg_out[src[i]], 1);
        atomicAdd(&g_deg_in[dst[i]], 1);
    }
}

// -------- scan1: block-local exclusive scan of deg_in; last block scans bsums --------
__global__ void k_scan1() {
    __shared__ int wt[8];
    __shared__ bool is_last;
    int tid = threadIdx.x;
    int lane = tid & 31;
    int wid = tid >> 5;
    int i = blockIdx.x * 256 + tid;

    int v = (i < NN) ? g_deg_in[i] : 0;
    int x = v;
#pragma unroll
    for (int off = 1; off < 32; off <<= 1) {
        int t = __shfl_up_sync(0xffffffffu, x, off);
        if (lane >= off) x += t;
    }
    if (lane == 31) wt[wid] = x;
    __syncthreads();
    if (wid == 0 && lane < 8) {
        int w = wt[lane];
#pragma unroll
        for (int off = 1; off < 8; off <<= 1) {
            int t = __shfl_up_sync(0x000000ffu, w, off);
            if (lane >= off) w += t;
        }
        wt[lane] = w;
    }
    __syncthreads();
    int base = (wid > 0) ? wt[wid - 1] : 0;
    int incl = base + x;
    if (i < NN) g_start[i] = incl - v;            // block-local exclusive
    if (tid == 255) g_bsum[blockIdx.x] = incl;    // block total

    // ---- last block scans the block sums (fused scan2) ----
    __threadfence();
    if (tid == 0) {
        int d = atomicAdd(&g_scan_done, 1);
        is_last = (d == (int)gridDim.x - 1);
    }
    __syncthreads();
    if (!is_last) return;
    __threadfence();

    int v0 = (2 * tid < SCAN_BLOCKS) ? g_bsum[2 * tid] : 0;
    int v1 = (2 * tid + 1 < SCAN_BLOCKS) ? g_bsum[2 * tid + 1] : 0;
    int p = v0 + v1;
    int y = p;
#pragma unroll
    for (int off = 1; off < 32; off <<= 1) {
        int t = __shfl_up_sync(0xffffffffu, y, off);
        if (lane >= off) y += t;
    }
    __syncthreads();   // wt reuse barrier
    if (lane == 31) wt[wid] = y;
    __syncthreads();
    if (wid == 0 && lane < 8) {
        int w = wt[lane];
#pragma unroll
        for (int off = 1; off < 8; off <<= 1) {
            int t = __shfl_up_sync(0x000000ffu, w, off);
            if (lane >= off) w += t;
        }
        wt[lane] = w;
    }
    __syncthreads();
    int base2 = (wid > 0) ? wt[wid - 1] : 0;
    int ex = base2 + y - p;   // exclusive pair-offset
    if (2 * tid < SCAN_BLOCKS) g_bsum[2 * tid] = ex;
    if (2 * tid + 1 < SCAN_BLOCKS) g_bsum[2 * tid + 1] = ex + v0;
}

// -------- CSR placement: pos = start_local + bsum + relative ticket --------
__global__ void k_place(const int* __restrict__ src, const int* __restrict__ dst) {
    int i = blockIdx.x * blockDim.x + threadIdx.x;
    if (i < NE) {
        int d = dst[i];
        int rel = atomicAdd(&g_cur0[d], 1);
        g_esrc[g_start[d] + g_bsum[d >> 8] + rel] = src[i];
    }
}

// ============================================================================
// TF32 tensor-core GEMM helpers (mma.sync m16n8k8)
// ============================================================================
__device__ __forceinline__ uint32_t f2tf32(float f) {
    uint32_t r;
    asm("cvt.rna.tf32.f32 %0, %1;" : "=r"(r) : "f"(f));
    return r;
}

__device__ __forceinline__ void mma_tf32(float c[4],
                                         uint32_t a0, uint32_t a1,
                                         uint32_t a2, uint32_t a3,
                                         uint32_t b0, uint32_t b1) {
    asm volatile(
        "mma.sync.aligned.m16n8k8.row.col.f32.tf32.tf32.f32 "
        "{%0,%1,%2,%3}, {%4,%5,%6,%7}, {%8,%9}, {%0,%1,%2,%3};"
        : "+f"(c[0]), "+f"(c[1]), "+f"(c[2]), "+f"(c[3])
        : "r"(a0), "r"(a1), "r"(a2), "r"(a3), "r"(b0), "r"(b1));
}

__device__ __forceinline__ float deg2norm(int deg) {
    return rsqrtf(fmaxf((float)deg, 1.f));
}

#define ASTR 36
#define BSTR 72
#define KCHUNK 32

// ============================================================================
// GEMM1: x1 = ((h @ W1) * norm_src)  -> fp16 store; norm inline from deg_out
// ============================================================================
__global__ __launch_bounds__(256) void k_gemm1(const float* __restrict__ h,
                                               const float* __restrict__ W1) {
    __shared__ uint32_t As[128 * ASTR];
    __shared__ uint32_t Bs[KCHUNK * BSTR];
    int tid = threadIdx.x;
    int w = tid >> 5;
    int lane = tid & 31;
    int q = lane >> 2;
    int cc = lane & 3;
    int row0 = blockIdx.x * 128;

    float c[8][4];
#pragma unroll
    for (int nt = 0; nt < 8; nt++)
#pragma unroll
        for (int j = 0; j < 4; j++) c[nt][j] = 0.f;

#pragma unroll 1
    for (int kc = 0; kc < IND / KCHUNK; kc++) {
        int k0 = kc * KCHUNK;
        __syncthreads();
        for (int i = tid; i < KCHUNK * HD; i += 256) {
            int kk = i >> 6, n = i & 63;
            Bs[kk * BSTR + n] = f2tf32(W1[(k0 + kk) * HD + n]);
        }
        for (int i = tid; i < 128 * KCHUNK; i += 256) {
            int r = i >> 5, kk = i & 31;
            int row = row0 + r;
            float v = (row < NN) ? h[row * IND + k0 + kk] : 0.f;
            As[r * ASTR + kk] = f2tf32(v);
        }
        __syncthreads();

        const uint32_t* ap = As + (w * 16 + q) * ASTR + cc;
#pragma unroll
        for (int ks = 0; ks < 4; ks++) {
            uint32_t a0 = ap[ks * 8];
            uint32_t a1 = ap[8 * ASTR + ks * 8];
            uint32_t a2 = ap[ks * 8 + 4];
            uint32_t a3 = ap[8 * ASTR + ks * 8 + 4];
            const uint32_t* bp = Bs + (ks * 8 + cc) * BSTR + q;
#pragma unroll
            for (int nt = 0; nt < 8; nt++) {
                uint32_t b0 = bp[nt * 8];
                uint32_t b1 = bp[4 * BSTR + nt * 8];
                mma_tf32(c[nt], a0, a1, a2, a3, b0, b1);
            }
        }
    }

    int r0g = row0 + w * 16 + q;
    int r1g = r0g + 8;
    float ns0 = (r0g < NN) ? deg2norm(g_deg_out[r0g]) : 0.f;
    float ns1 = (r1g < NN) ? deg2norm(g_deg_out[r1g]) : 0.f;
#pragma unroll
    for (int nt = 0; nt < 8; nt++) {
        int h2col = nt * 4 + cc;
        if (r0g < NN)
            g_x1h[r0g * 32 + h2col] = __floats2half2_rn(c[nt][0] * ns0, c[nt][1] * ns0);
        if (r1g < NN)
            g_x1h[r1g * 32 + h2col] = __floats2half2_rn(c[nt][2] * ns1, c[nt][3] * ns1);
    }
}

// ============================================================================
// GEMM2: x2 = (elu(agg1*norm_dst + b1) * norm_src) @ W2 -> fp16 store
// norms precomputed into smem from integer degrees
// ============================================================================
__global__ __launch_bounds__(256) void k_gemm2(const float* __restrict__ b1,
                                               const float* __restrict__ W2) {
    __shared__ uint32_t As[128 * ASTR];
    __shared__ uint32_t Bs[KCHUNK * BSTR];
    __shared__ float b1s[HD];
    __shared__ float nds[128], nss[128];
    int tid = threadIdx.x;
    int w = tid >> 5;
    int lane = tid & 31;
    int q = lane >> 2;
    int cc = lane & 3;
    int row0 = blockIdx.x * 128;

    if (tid < HD) b1s[tid] = b1[tid];
    if (tid < 128) {
        int row = row0 + tid;
        nds[tid] = (row < NN) ? deg2norm(g_deg_in[row]) : 0.f;
        nss[tid] = (row < NN) ? deg2norm(g_deg_out[row]) : 0.f;
    }

    float c[8][4];
#pragma unroll
    for (int nt = 0; nt < 8; nt++)
#pragma unroll
        for (int j = 0; j < 4; j++) c[nt][j] = 0.f;

#pragma unroll 1
    for (int kc = 0; kc < HD / KCHUNK; kc++) {
        int k0 = kc * KCHUNK;
        __syncthreads();
        for (int i = tid; i < KCHUNK * HD; i += 256) {
            int kk = i >> 6, n = i & 63;
            Bs[kk * BSTR + n] = f2tf32(W2[(k0 + kk) * HD + n]);
        }
        for (int i = tid; i < 128 * KCHUNK; i += 256) {
            int r = i >> 5, kk = i & 31;
            int row = row0 + r;
            float v = 0.f;
            if (row < NN) {
                int k = k0 + kk;
                v = g_agg1[row * HD + k] * nds[r] + b1s[k];
                v = (v > 0.f) ? v : expm1f(v);
                v *= nss[r];
            }
            As[r * ASTR + kk] = f2tf32(v);
        }
        __syncthreads();

        const uint32_t* ap = As + (w * 16 + q) * ASTR + cc;
#pragma unroll
        for (int ks = 0; ks < 4; ks++) {
            uint32_t a0 = ap[ks * 8];
            uint32_t a1 = ap[8 * ASTR + ks * 8];
            uint32_t a2 = ap[ks * 8 + 4];
            uint32_t a3 = ap[8 * ASTR + ks * 8 + 4];
            const uint32_t* bp = Bs + (ks * 8 + cc) * BSTR + q;
#pragma unroll
            for (int nt = 0; nt < 8; nt++) {
                uint32_t b0 = bp[nt * 8];
                uint32_t b1r = bp[4 * BSTR + nt * 8];
                mma_tf32(c[nt], a0, a1, a2, a3, b0, b1r);
            }
        }
    }

    int r0g = row0 + w * 16 + q;
    int r1g = r0g + 8;
#pragma unroll
    for (int nt = 0; nt < 8; nt++) {
        int h2col = nt * 4 + cc;
        if (r0g < NN)
            g_x2h[r0g * 32 + h2col] = __floats2half2_rn(c[nt][0], c[nt][1]);
        if (r1g < NN)
            g_x2h[r1g * 32 + h2col] = __floats2half2_rn(c[nt][2], c[nt][3]);
    }
}

// ============================================================================
// CSR aggregation: warp per node; 16 lanes cover one 128B row via uint2,
// so each gather LDG.64 fetches TWO edges' rows (lanes 0-15 edge e, 16-31 e+1).
// Halves LDG instruction count vs half2/lane. fp32 accumulation, no atomics.
// Result: lanes 0-15 hold float4 for cols 4c..4c+3 after shfl-combine.
// ============================================================================
__device__ __forceinline__ float4 agg_row_u2(const uint2* __restrict__ xh,
                                             int n, int lane) {
    int sub = lane >> 4;   // which edge of the pair
    int c = lane & 15;     // uint2 column (4 half cols)
    int start = g_start[n] + g_bsum[n >> 8];
    int end = start + g_deg_in[n];
    float4 acc = make_float4(0.f, 0.f, 0.f, 0.f);
    int e = start;

    for (; e + 8 <= end; e += 8) {
#pragma unroll
        for (int kp = 0; kp < 4; kp++) {
            int s = __ldg(&g_esrc[e + 2 * kp + sub]);
            uint2 u = __ldg(&xh[s * 16 + c]);
            float2 f0 = __half22float2(*reinterpret_cast<__half2*>(&u.x));
            float2 f1 = __half22float2(*reinterpret_cast<__half2*>(&u.y));
            acc.x += f0.x; acc.y += f0.y;
            acc.z += f1.x; acc.w += f1.y;
        }
    }
    for (; e < end; e += 2) {
        int e2 = e + sub;
        if (e2 < end) {
            int s = __ldg(&g_esrc[e2]);
            uint2 u = __ldg(&xh[s * 16 + c]);
            float2 f0 = __half22float2(*reinterpret_cast<__half2*>(&u.x));
            float2 f1 = __half22float2(*reinterpret_cast<__half2*>(&u.y));
            acc.x += f0.x; acc.y += f0.y;
            acc.z += f1.x; acc.w += f1.y;
        }
    }
    acc.x += __shfl_down_sync(0xffffffffu, acc.x, 16);
    acc.y += __shfl_down_sync(0xffffffffu, acc.y, 16);
    acc.z += __shfl_down_sync(0xffffffffu, acc.z, 16);
    acc.w += __shfl_down_sync(0xffffffffu, acc.w, 16);
    return acc;
}

__global__ __launch_bounds__(256) void k_agg1() {
    int n = (blockIdx.x * 256 + threadIdx.x) >> 5;
    int lane = threadIdx.x & 31;
    if (n >= NN) return;
    float4 acc = agg_row_u2(reinterpret_cast<const uint2*>(g_x1h), n, lane);
    if (lane < 16)
        reinterpret_cast<float4*>(g_agg1)[n * 16 + lane] = acc;
}

// layer-2 aggregation with fused finalize: out = agg*norm_dst + b2
__global__ __launch_bounds__(256) void k_agg2(float* __restrict__ out,
                                              const float* __restrict__ b2) {
    int n = (blockIdx.x * 256 + threadIdx.x) >> 5;
    int lane = threadIdx.x & 31;
    if (n >= NN) return;
    float4 acc = agg_row_u2(reinterpret_cast<const uint2*>(g_x2h), n, lane);
    if (lane < 16) {
        float nd = deg2norm(g_deg_in[n]);
        float4 bb = __ldg(reinterpret_cast<const float4*>(b2) + lane);
        float4 o = make_float4(acc.x * nd + bb.x, acc.y * nd + bb.y,
                               acc.z * nd + bb.z, acc.w * nd + bb.w);
        reinterpret_cast<float4*>(out)[n * 16 + lane] = o;
    }
}

extern "C" void kernel_launch(void* const* d_in, const int* in_sizes, int n_in,
                              void* d_out, int out_size) {
    const float* h   = (const float*)d_in[0];
    const int*   src = (const int*)d_in[1];
    const int*   dst = (const int*)d_in[2];
    const float* W1  = (const float*)d_in[3];
    const float* b1  = (const float*)d_in[4];
    const float* W2  = (const float*)d_in[5];
    const float* b2  = (const float*)d_in[6];
    float* out = (float*)d_out;

    const int GBLK = (NN + 127) / 128;           // 782
    const int AGG_BLK = (NN * 32 + 255) / 256;   // warp per node

    // ---- graph preprocessing (CSR by dst), 4 launches ----
    k_init<<<(NN + 255) / 256, 256>>>();
    k_deg<<<(NE + 255) / 256, 256>>>(src, dst);
    k_scan1<<<SCAN_BLOCKS, 256>>>();             // + fused block-sum scan
    k_place<<<(NE + 255) / 256, 256>>>(src, dst);

    // ---- layer 1 ----
    k_gemm1<<<GBLK, 256>>>(h, W1);
    k_agg1<<<AGG_BLK, 256>>>();

    // ---- layer 2 ----
    k_gemm2<<<GBLK, 256>>>(b1, W2);
    k_agg2<<<AGG_BLK, 256>>>(out, b2);
}